// round 8
// baseline (speedup 1.0000x reference)
#include <cuda_runtime.h>
#include <cuda_bf16.h>
#include <math.h>
#include <stdint.h>

// Problem constants
#define B_SZ   4
#define L_SZ   1024
#define D_SZ   768
#define DI_SZ  1536
#define DI2_SZ 3072
#define N_ST   16
#define DTR_SZ 48
#define XDBL_W 80           // DTR + 2*N
#define M_ROWS 4096         // B*L
#define KSPLIT 4
#define XPART  (M_ROWS * XDBL_W)
#define KDT    64           // padded dt K

// Scratch (device globals; no allocation allowed)
__device__ float g_xz   [M_ROWS * DI2_SZ];
__device__ float g_xc   [M_ROWS * DI_SZ];
__device__ float g_xpart[KSPLIT * XPART];
__device__ float g_xdbl [M_ROWS * XDBL_W];
__device__ float g_delta[M_ROWS * DI_SZ];

// pre-split bf16 operands (hi/lo)
__device__ __align__(16) __nv_bfloat16 g_xnh [M_ROWS * D_SZ],  g_xnl [M_ROWS * D_SZ];
__device__ __align__(16) __nv_bfloat16 g_xch [M_ROWS * DI_SZ], g_xcl [M_ROWS * DI_SZ];
__device__ __align__(16) __nv_bfloat16 g_xdth[M_ROWS * KDT],   g_xdtl[M_ROWS * KDT];
__device__ __align__(16) __nv_bfloat16 g_yh  [M_ROWS * DI_SZ], g_yl  [M_ROWS * DI_SZ];
__device__ __align__(16) __nv_bfloat16 g_winh[DI2_SZ * D_SZ],  g_winl[DI2_SZ * D_SZ];
__device__ __align__(16) __nv_bfloat16 g_wxh [XDBL_W * DI_SZ], g_wxl [XDBL_W * DI_SZ];
__device__ __align__(16) __nv_bfloat16 g_wdth[DI_SZ * KDT],    g_wdtl[DI_SZ * KDT];
__device__ __align__(16) __nv_bfloat16 g_wouth[D_SZ * DI_SZ],  g_woutl[D_SZ * DI_SZ];

__device__ __forceinline__ void mma16(float* d,
                                      const uint32_t* a, const uint32_t* b) {
    asm volatile(
        "mma.sync.aligned.m16n8k16.row.col.f32.bf16.bf16.f32 "
        "{%0,%1,%2,%3}, {%4,%5,%6,%7}, {%8,%9}, {%0,%1,%2,%3};"
        : "+f"(d[0]), "+f"(d[1]), "+f"(d[2]), "+f"(d[3])
        : "r"(a[0]), "r"(a[1]), "r"(a[2]), "r"(a[3]), "r"(b[0]), "r"(b[1]));
}

__device__ __forceinline__ void ldsm4(uint32_t& r0, uint32_t& r1,
                                      uint32_t& r2, uint32_t& r3, uint32_t a) {
    asm volatile("ldmatrix.sync.aligned.m8n8.x4.shared.b16 {%0,%1,%2,%3}, [%4];"
                 : "=r"(r0), "=r"(r1), "=r"(r2), "=r"(r3) : "r"(a));
}

__device__ __forceinline__ void cpa(uint32_t d, const void* s, int sz) {
    asm volatile("cp.async.cg.shared.global [%0], [%1], 16, %2;"
                 :: "r"(d), "l"(s), "r"(sz) : "memory");
}

__device__ __forceinline__ uint32_t s2u(const void* p) {
    uint32_t a;
    asm("{ .reg .u64 t; cvta.to.shared.u64 t, %1; cvt.u32.u64 %0, t; }"
        : "=r"(a) : "l"(p));
    return a;
}

__device__ __forceinline__ void bsplit(float v, __nv_bfloat16& h, __nv_bfloat16& l) {
    h = __float2bfloat16_rn(v);
    l = __float2bfloat16_rn(v - __bfloat162float(h));
}

// ---------------------------------------------------------------------------
// LayerNorm -> split bf16 xn
// ---------------------------------------------------------------------------
__global__ void ln_kernel(const float* __restrict__ x,
                          const float* __restrict__ gam,
                          const float* __restrict__ bet)
{
    int row = blockIdx.x;
    const float* xr = x + (size_t)row * D_SZ;
    float v[3];
    float s = 0.f, sq = 0.f;
#pragma unroll
    for (int i = 0; i < 3; i++) {
        v[i] = xr[threadIdx.x + i * 256];
        s += v[i];
        sq += v[i] * v[i];
    }
#pragma unroll
    for (int o = 16; o > 0; o >>= 1) {
        s  += __shfl_xor_sync(0xffffffffu, s, o);
        sq += __shfl_xor_sync(0xffffffffu, sq, o);
    }
    __shared__ float ss[8], ssq[8];
    int w = threadIdx.x >> 5, lane = threadIdx.x & 31;
    if (lane == 0) { ss[w] = s; ssq[w] = sq; }
    __syncthreads();
    if (w == 0) {
        s  = (lane < 8) ? ss[lane]  : 0.f;
        sq = (lane < 8) ? ssq[lane] : 0.f;
#pragma unroll
        for (int o = 4; o > 0; o >>= 1) {
            s  += __shfl_xor_sync(0xffffffffu, s, o);
            sq += __shfl_xor_sync(0xffffffffu, sq, o);
        }
        if (lane == 0) { ss[0] = s; ssq[0] = sq; }
    }
    __syncthreads();
    float mu  = ss[0] * (1.f / D_SZ);
    float var = ssq[0] * (1.f / D_SZ) - mu * mu;
    float rs  = rsqrtf(var + 1e-6f);
#pragma unroll
    for (int i = 0; i < 3; i++) {
        int c = threadIdx.x + i * 256;
        float o = (v[i] - mu) * rs * gam[c] + bet[c];
        __nv_bfloat16 hh, ll;
        bsplit(o, hh, ll);
        size_t idx = (size_t)row * D_SZ + c;
        g_xnh[idx] = hh; g_xnl[idx] = ll;
    }
}

// ---------------------------------------------------------------------------
// Weight split kernels
// ---------------------------------------------------------------------------
__global__ void split_kernel(const float* __restrict__ src,
                             __nv_bfloat16* __restrict__ h,
                             __nv_bfloat16* __restrict__ l, int n)
{
    int i = blockIdx.x * 256 + threadIdx.x;
    if (i < n) {
        __nv_bfloat16 hh, ll;
        bsplit(src[i], hh, ll);
        h[i] = hh; l[i] = ll;
    }
}

__global__ void split_wdt_kernel(const float* __restrict__ src)  // 1536x48 -> 1536x64 pad
{
    int i = blockIdx.x * 256 + threadIdx.x;
    if (i < DI_SZ * KDT) {
        int row = i >> 6, col = i & 63;
        float v = (col < DTR_SZ) ? src[row * DTR_SZ + col] : 0.f;
        __nv_bfloat16 hh, ll;
        bsplit(v, hh, ll);
        g_wdth[i] = hh; g_wdtl[i] = ll;
    }
}

// ---------------------------------------------------------------------------
// bf16 pre-split NT GEMM: cp.async 2-stage + ldmatrix + mma only.
// Tile 128x128x32, 512 threads (16 warps 4x4), warp tile 32x32.
// K must be a multiple of 32 (operands pre-padded).
// EPI 0: plain   EPI 1: softplus(acc + bias[n])   EPI 2: relu(acc)+resid
// ---------------------------------------------------------------------------
#define RSB    80                 // smem bytes per row (64 data + 16 pad)
#define TILEB  (128 * RSB)        // 10240
#define STAGEB (4 * TILEB)        // 40960: Ahi, Alo, Bhi, Blo
#define GSMEM  (2 * STAGEB)       // 81920

template <int EPI>
__global__ __launch_bounds__(512)
void mgemm(const __nv_bfloat16* __restrict__ Ah,
           const __nv_bfloat16* __restrict__ Al, int lda,
           const __nv_bfloat16* __restrict__ Bh,
           const __nv_bfloat16* __restrict__ Bl, int ldb,
           float* __restrict__ C, int M, int N, int K,
           const float* __restrict__ bias,
           const float* __restrict__ resid, size_t zC)
{
    extern __shared__ __align__(16) char smraw[];
    uint32_t smbase = s2u(smraw);

    Ah += (size_t)blockIdx.z * K;
    Al += (size_t)blockIdx.z * K;
    C  += (size_t)blockIdx.z * zC;

    int tid = threadIdx.x;
    int wid = tid >> 5, lane = tid & 31;
    int wm = (wid & 3) * 32;
    int wn = (wid >> 2) * 32;
    int grp = lane >> 2, qd = lane & 3;
    int row0 = blockIdx.y * 128, col0 = blockIdx.x * 128;

    float acc[2][4][4];
#pragma unroll
    for (int mi = 0; mi < 2; mi++)
#pragma unroll
        for (int ni = 0; ni < 4; ni++)
#pragma unroll
            for (int e = 0; e < 4; e++) acc[mi][ni][e] = 0.f;

    const int nch = K / 32;

    // cp.async coords: 512 threads x 16B covers one 128x64B tile
    int crow = tid >> 2;           // 0..127
    int c16  = tid & 3;            // 16B column

    int bn  = col0 + crow;
    int bsz = (bn < N) ? 16 : 0;
    size_t brow_ofs = (size_t)((bn < N) ? bn : 0) * ldb;

    auto issue = [&](int c) {
        uint32_t st = smbase + (uint32_t)(c & 1) * STAGEB;
        uint32_t da = st + crow * RSB + c16 * 16;
        size_t aofs = (size_t)(row0 + crow) * lda + c * 32 + c16 * 8;
        cpa(da,             Ah + aofs, 16);
        cpa(da + TILEB,     Al + aofs, 16);
        size_t bofs = brow_ofs + c * 32 + c16 * 8;
        cpa(da + 2 * TILEB, Bh + bofs, bsz);
        cpa(da + 3 * TILEB, Bl + bofs, bsz);
        asm volatile("cp.async.commit_group;" ::: "memory");
    };

    issue(0);

    int arow = lane & 15;
    int asel = (lane >> 4) * 16;
    int brow = ((lane >> 4) << 3) + (lane & 7);
    int bsel = ((lane >> 3) & 1) * 16;

    for (int c = 0; c < nch; c++) {
        if (c + 1 < nch) {
            issue(c + 1);
            asm volatile("cp.async.wait_group 1;" ::: "memory");
        } else {
            asm volatile("cp.async.wait_group 0;" ::: "memory");
        }
        __syncthreads();

        uint32_t stA  = smbase + (uint32_t)(c & 1) * STAGEB;
        uint32_t stAl = stA + TILEB;
        uint32_t stB  = stA + 2 * TILEB;
        uint32_t stBl = stA + 3 * TILEB;

#pragma unroll
        for (int ks = 0; ks < 2; ks++) {
            int kb = ks * 32;   // byte offset of k-half
            uint32_t ahi[2][4], alo[2][4], bhi[4][2], blo[4][2];
#pragma unroll
            for (int mi = 0; mi < 2; mi++) {
                uint32_t ad = stA + (wm + mi * 16 + arow) * RSB + kb + asel;
                ldsm4(ahi[mi][0], ahi[mi][1], ahi[mi][2], ahi[mi][3], ad);
            }
#pragma unroll
            for (int nb = 0; nb < 2; nb++) {
                uint32_t bd = stB + (wn + nb * 16 + brow) * RSB + kb + bsel;
                ldsm4(bhi[2 * nb][0], bhi[2 * nb][1],
                      bhi[2 * nb + 1][0], bhi[2 * nb + 1][1], bd);
            }
            // pass 1: hi*hi
#pragma unroll
            for (int mi = 0; mi < 2; mi++)
#pragma unroll
                for (int ni = 0; ni < 4; ni++)
                    mma16(acc[mi][ni], ahi[mi], bhi[ni]);
            // pass 2: lo*hi
#pragma unroll
            for (int mi = 0; mi < 2; mi++) {
                uint32_t ad = stAl + (wm + mi * 16 + arow) * RSB + kb + asel;
                ldsm4(alo[mi][0], alo[mi][1], alo[mi][2], alo[mi][3], ad);
            }
#pragma unroll
            for (int mi = 0; mi < 2; mi++)
#pragma unroll
                for (int ni = 0; ni < 4; ni++)
                    mma16(acc[mi][ni], alo[mi], bhi[ni]);
            // pass 3: hi*lo
#pragma unroll
            for (int nb = 0; nb < 2; nb++) {
                uint32_t bd = stBl + (wn + nb * 16 + brow) * RSB + kb + bsel;
                ldsm4(blo[2 * nb][0], blo[2 * nb][1],
                      blo[2 * nb + 1][0], blo[2 * nb + 1][1], bd);
            }
#pragma unroll
            for (int mi = 0; mi < 2; mi++)
#pragma unroll
                for (int ni = 0; ni < 4; ni++)
                    mma16(acc[mi][ni], ahi[mi], blo[ni]);
        }
        __syncthreads();
    }

    // epilogue: registers -> gmem
#pragma unroll
    for (int mi = 0; mi < 2; mi++) {
#pragma unroll
        for (int ni = 0; ni < 4; ni++) {
            int r  = row0 + wm + mi * 16 + grp;
            int cc = col0 + wn + ni * 8 + qd * 2;
            if (cc < N) {
#pragma unroll
                for (int h = 0; h < 2; h++) {
                    int rr = r + h * 8;
                    float v0 = acc[mi][ni][h * 2 + 0];
                    float v1 = acc[mi][ni][h * 2 + 1];
                    if (EPI == 1) {
                        v0 += bias[cc];
                        v1 += bias[cc + 1];
                        v0 = (v0 > 20.f) ? v0 : log1pf(__expf(v0));
                        v1 = (v1 > 20.f) ? v1 : log1pf(__expf(v1));
                    } else if (EPI == 2) {
                        v0 = fmaxf(v0, 0.f) + resid[(size_t)rr * N + cc];
                        v1 = fmaxf(v1, 0.f) + resid[(size_t)rr * N + cc + 1];
                    }
                    float2 o; o.x = v0; o.y = v1;
                    *(float2*)(C + (size_t)rr * N + cc) = o;
                }
            }
        }
    }
}

// ---------------------------------------------------------------------------
// Reduce split-K partials for x_dbl; emit f32 xdbl + padded split dt operand
// ---------------------------------------------------------------------------
__global__ void xdbl_reduce_kernel()
{
    int i = blockIdx.x * 256 + threadIdx.x;
    if (i < XPART) {
        float s = g_xpart[i] + g_xpart[i + XPART]
                + g_xpart[i + 2 * XPART] + g_xpart[i + 3 * XPART];
        g_xdbl[i] = s;
        int col = i % XDBL_W, row = i / XDBL_W;
        if (col < KDT) {
            float v = (col < DTR_SZ) ? s : 0.f;
            __nv_bfloat16 hh, ll;
            bsplit(v, hh, ll);
            g_xdth[row * KDT + col] = hh;
            g_xdtl[row * KDT + col] = ll;
        }
    }
}

// ---------------------------------------------------------------------------
// Causal depthwise conv (width 4) + bias + SiLU; f32 (scan) + split bf16
// ---------------------------------------------------------------------------
__global__ void conv_silu_kernel(const float* __restrict__ Wc,
                                 const float* __restrict__ bc)
{
    int gid = blockIdx.x * blockDim.x + threadIdx.x;
    if (gid >= (M_ROWS / 4) * DI_SZ) return;
    int d   = gid % DI_SZ;
    int blk = gid / DI_SZ;
    int b   = blk / (L_SZ / 4);
    int l0  = (blk % (L_SZ / 4)) * 4;
    int bl0 = b * L_SZ + l0;

    float w0 = Wc[d * 4 + 0], w1 = Wc[d * 4 + 1];
    float w2 = Wc[d * 4 + 2], w3 = Wc[d * 4 + 3];
    float bb = bc[d];

    float x[7];
#pragma unroll
    for (int k = 0; k < 7; k++) {
        int l = l0 - 3 + k;
        x[k] = (l >= 0) ? g_xz[(size_t)(bl0 - 3 + k) * DI2_SZ + d] : 0.f;
    }
#pragma unroll
    for (int i = 0; i < 4; i++) {
        float acc = bb;
        acc = fmaf(w0, x[i],     acc);
        acc = fmaf(w1, x[i + 1], acc);
        acc = fmaf(w2, x[i + 2], acc);
        acc = fmaf(w3, x[i + 3], acc);
        float v = acc / (1.f + __expf(-acc));
        size_t ofs = (size_t)(bl0 + i) * DI_SZ + d;
        g_xc[ofs] = v;
        __nv_bfloat16 hh, ll;
        bsplit(v, hh, ll);
        g_xch[ofs] = hh; g_xcl[ofs] = ll;
    }
}

// ---------------------------------------------------------------------------
// Selective scan + skip + gate; emits split bf16 y
// ---------------------------------------------------------------------------
__global__ __launch_bounds__(256)
void scan_kernel(const float* __restrict__ A_log,
                 const float* __restrict__ Dpar)
{
    int gtid  = blockIdx.x * 256 + threadIdx.x;
    int chain = gtid >> 4;          // 0..6143
    int n     = gtid & 15;
    int b     = chain / DI_SZ;
    int d     = chain % DI_SZ;

    float a  = -__expf(A_log[d * N_ST + n]);
    float dp = Dpar[d];
    float h  = 0.f;
    int base = b * L_SZ;

    const float* pd = g_delta + (size_t)base * DI_SZ + d;
    const float* pu = g_xc    + (size_t)base * DI_SZ + d;
    const float* px = g_xdbl  + (size_t)base * XDBL_W + DTR_SZ + n;
    const float* pz = g_xz    + (size_t)base * DI2_SZ + DI_SZ + d;
    __nv_bfloat16* pyh = g_yh + (size_t)base * DI_SZ + d;
    __nv_bfloat16* pyl = g_yl + (size_t)base * DI_SZ + d;

    float dl = pd[0], u = pu[0], Bv = px[0], Cv = px[N_ST], z = pz[0];

#pragma unroll 4
    for (int l = 0; l < L_SZ; l++) {
        float dl2 = 0.f, u2 = 0.f, Bv2 = 0.f, Cv2 = 0.f, z2 = 0.f;
        if (l + 1 < L_SZ) {
            pd += DI_SZ; pu += DI_SZ; px += XDBL_W; pz += DI2_SZ;
            dl2 = pd[0]; u2 = pu[0]; Bv2 = px[0]; Cv2 = px[N_ST]; z2 = pz[0];
        }
        float dA = __expf(dl * a);
        h = fmaf(dA, h, dl * Bv * u);
        float s = h * Cv;
        s += __shfl_xor_sync(0xffffffffu, s, 8);
        s += __shfl_xor_sync(0xffffffffu, s, 4);
        s += __shfl_xor_sync(0xffffffffu, s, 2);
        s += __shfl_xor_sync(0xffffffffu, s, 1);
        if (n == 0) {
            float sil = z / (1.f + __expf(-z));
            float v = (s + u * dp) * sil;
            __nv_bfloat16 hh, ll;
            bsplit(v, hh, ll);
            pyh[0] = hh; pyl[0] = ll;
        }
        pyh += DI_SZ; pyl += DI_SZ;
        dl = dl2; u = u2; Bv = Bv2; Cv = Cv2; z = z2;
    }
}

// ---------------------------------------------------------------------------
extern "C" void kernel_launch(void* const* d_in, const int* in_sizes, int n_in,
                              void* d_out, int out_size)
{
    const float* input   = (const float*)d_in[0];
    const float* ln_g    = (const float*)d_in[1];
    const float* ln_b    = (const float*)d_in[2];
    const float* W_in    = (const float*)d_in[3];
    const float* W_conv  = (const float*)d_in[4];
    const float* b_conv  = (const float*)d_in[5];
    const float* W_x     = (const float*)d_in[6];
    const float* W_dt    = (const float*)d_in[7];
    const float* b_dt    = (const float*)d_in[8];
    const float* A_log   = (const float*)d_in[9];
    const float* D_param = (const float*)d_in[10];
    const float* W_out   = (const float*)d_in[11];
    float* out = (float*)d_out;

    float *xpart;
    __nv_bfloat16 *xnh, *xnl, *xch, *xcl, *xdth, *xdtl, *yh, *yl;
    __nv_bfloat16 *winh, *winl, *wxh, *wxl, *wdth, *wdtl, *wouth, *woutl;
    cudaGetSymbolAddress((void**)&xpart, g_xpart);
    cudaGetSymbolAddress((void**)&xnh, g_xnh);   cudaGetSymbolAddress((void**)&xnl, g_xnl);
    cudaGetSymbolAddress((void**)&xch, g_xch);   cudaGetSymbolAddress((void**)&xcl, g_xcl);
    cudaGetSymbolAddress((void**)&xdth, g_xdth); cudaGetSymbolAddress((void**)&xdtl, g_xdtl);
    cudaGetSymbolAddress((void**)&yh, g_yh);     cudaGetSymbolAddress((void**)&yl, g_yl);
    cudaGetSymbolAddress((void**)&winh, g_winh); cudaGetSymbolAddress((void**)&winl, g_winl);
    cudaGetSymbolAddress((void**)&wxh, g_wxh);   cudaGetSymbolAddress((void**)&wxl, g_wxl);
    cudaGetSymbolAddress((void**)&wdth, g_wdth); cudaGetSymbolAddress((void**)&wdtl, g_wdtl);
    cudaGetSymbolAddress((void**)&wouth, g_wouth); cudaGetSymbolAddress((void**)&woutl, g_woutl);

    float *xz, *xc, *xdbl, *delta;
    cudaGetSymbolAddress((void**)&xz,    g_xz);
    cudaGetSymbolAddress((void**)&xc,    g_xc);
    cudaGetSymbolAddress((void**)&xdbl,  g_xdbl);
    cudaGetSymbolAddress((void**)&delta, g_delta);

    cudaFuncSetAttribute(mgemm<0>, cudaFuncAttributeMaxDynamicSharedMemorySize, GSMEM);
    cudaFuncSetAttribute(mgemm<1>, cudaFuncAttributeMaxDynamicSharedMemorySize, GSMEM);
    cudaFuncSetAttribute(mgemm<2>, cudaFuncAttributeMaxDynamicSharedMemorySize, GSMEM);

    // weight splits (one-time per call; overlap with LN)
    split_kernel<<<(DI2_SZ * D_SZ + 255) / 256, 256>>>(W_in,  winh,  winl,  DI2_SZ * D_SZ);
    split_kernel<<<(XDBL_W * DI_SZ + 255) / 256, 256>>>(W_x,  wxh,   wxl,   XDBL_W * DI_SZ);
    split_wdt_kernel<<<(DI_SZ * KDT + 255) / 256, 256>>>(W_dt);
    split_kernel<<<(D_SZ * DI_SZ + 255) / 256, 256>>>(W_out, wouth, woutl, D_SZ * DI_SZ);

    // 1. LayerNorm -> split xn
    ln_kernel<<<M_ROWS, 256>>>(input, ln_g, ln_b);

    // 2. in-proj: xz = xn @ W_in^T   (4096 x 3072 x 768)
    {
        dim3 g(DI2_SZ / 128, M_ROWS / 128, 1);
        mgemm<0><<<g, 512, GSMEM>>>(xnh, xnl, D_SZ, winh, winl, D_SZ, xz,
                                    M_ROWS, DI2_SZ, D_SZ, nullptr, nullptr, 0);
    }

    // 3. causal depthwise conv + SiLU -> xc (f32 + split)
    {
        int total = (M_ROWS / 4) * DI_SZ;
        conv_silu_kernel<<<(total + 255) / 256, 256>>>(W_conv, b_conv);
    }

    // 4. x_dbl = xc @ W_x^T   (4096 x 80 x 1536) — split-K x4
    {
        dim3 g(1, M_ROWS / 128, KSPLIT);
        mgemm<0><<<g, 512, GSMEM>>>(xch, xcl, DI_SZ, wxh, wxl, DI_SZ, xpart,
                                    M_ROWS, XDBL_W, DI_SZ / KSPLIT,
                                    nullptr, nullptr, (size_t)XPART);
        xdbl_reduce_kernel<<<(XPART + 255) / 256, 256>>>();
    }

    // 5. delta = softplus(dt @ W_dt^T + b_dt)   (4096 x 1536 x 64pad)
    {
        dim3 g(DI_SZ / 128, M_ROWS / 128, 1);
        mgemm<1><<<g, 512, GSMEM>>>(xdth, xdtl, KDT, wdth, wdtl, KDT, delta,
                                    M_ROWS, DI_SZ, KDT, b_dt, nullptr, 0);
    }

    // 6. selective scan + skip + gating -> split y
    {
        int threads = B_SZ * DI_SZ * N_ST;   // 98304
        scan_kernel<<<threads / 256, 256>>>(A_log, D_param);
    }

    // 7. out = relu(y @ W_out^T) + input   (4096 x 768 x 1536)
    {
        dim3 g(D_SZ / 128, M_ROWS / 128, 1);
        mgemm<2><<<g, 512, GSMEM>>>(yh, yl, DI_SZ, wouth, woutl, DI_SZ, out,
                                    M_ROWS, D_SZ, DI_SZ, nullptr, input, 0);
    }
}

// round 9
// speedup vs baseline: 1.4191x; 1.4191x over previous
#include <cuda_runtime.h>
#include <cuda_bf16.h>
#include <math.h>
#include <stdint.h>

// Problem constants
#define B_SZ   4
#define L_SZ   1024
#define D_SZ   768
#define DI_SZ  1536
#define DI2_SZ 3072
#define N_ST   16
#define DTR_SZ 48
#define XDBL_W 80           // DTR + 2*N
#define M_ROWS 4096         // B*L
#define KSPLIT 4
#define XPART  (M_ROWS * XDBL_W)

// Scratch (device globals; no allocation allowed)
__device__ float g_xn  [M_ROWS * D_SZ];
__device__ float g_xz  [M_ROWS * DI2_SZ];
__device__ float g_xc  [M_ROWS * DI_SZ];
__device__ float g_xpart[KSPLIT * XPART];
__device__ float g_xdbl[M_ROWS * XDBL_W];
__device__ float g_delta[M_ROWS * DI_SZ];
__device__ float g_y   [M_ROWS * DI_SZ];

__device__ __forceinline__ void mma16(float* d,
                                      const uint32_t* a, const uint32_t* b) {
    asm volatile(
        "mma.sync.aligned.m16n8k16.row.col.f32.bf16.bf16.f32 "
        "{%0,%1,%2,%3}, {%4,%5,%6,%7}, {%8,%9}, {%0,%1,%2,%3};"
        : "+f"(d[0]), "+f"(d[1]), "+f"(d[2]), "+f"(d[3])
        : "r"(a[0]), "r"(a[1]), "r"(a[2]), "r"(a[3]), "r"(b[0]), "r"(b[1]));
}

__device__ __forceinline__ void ldsm4(uint32_t& r0, uint32_t& r1,
                                      uint32_t& r2, uint32_t& r3, uint32_t a) {
    asm volatile("ldmatrix.sync.aligned.m8n8.x4.shared.b16 {%0,%1,%2,%3}, [%4];"
                 : "=r"(r0), "=r"(r1), "=r"(r2), "=r"(r3) : "r"(a));
}

__device__ __forceinline__ uint32_t s2u(const void* p) {
    uint32_t a;
    asm("{ .reg .u64 t; cvta.to.shared.u64 t, %1; cvt.u32.u64 %0, t; }"
        : "=r"(a) : "l"(p));
    return a;
}

// split float4 into 4x bf16 hi (8B) and 4x bf16 lo (8B)
__device__ __forceinline__ void split4(float4 v, uint2& h, uint2& l) {
    __nv_bfloat16 hx = __float2bfloat16_rn(v.x);
    __nv_bfloat16 hy = __float2bfloat16_rn(v.y);
    __nv_bfloat16 hz = __float2bfloat16_rn(v.z);
    __nv_bfloat16 hw = __float2bfloat16_rn(v.w);
    __nv_bfloat162 h0 = __halves2bfloat162(hx, hy);
    __nv_bfloat162 h1 = __halves2bfloat162(hz, hw);
    __nv_bfloat162 l0 = __halves2bfloat162(
        __float2bfloat16_rn(v.x - __bfloat162float(hx)),
        __float2bfloat16_rn(v.y - __bfloat162float(hy)));
    __nv_bfloat162 l1 = __halves2bfloat162(
        __float2bfloat16_rn(v.z - __bfloat162float(hz)),
        __float2bfloat16_rn(v.w - __bfloat162float(hw)));
    h.x = *(uint32_t*)&h0; h.y = *(uint32_t*)&h1;
    l.x = *(uint32_t*)&l0; l.y = *(uint32_t*)&l1;
}

// ---------------------------------------------------------------------------
// LayerNorm: one block (256 thr) per row of 768
// ---------------------------------------------------------------------------
__global__ void ln_kernel(const float* __restrict__ x,
                          const float* __restrict__ gam,
                          const float* __restrict__ bet)
{
    int row = blockIdx.x;
    const float* xr = x + (size_t)row * D_SZ;
    float v[3];
    float s = 0.f, sq = 0.f;
#pragma unroll
    for (int i = 0; i < 3; i++) {
        v[i] = xr[threadIdx.x + i * 256];
        s += v[i];
        sq += v[i] * v[i];
    }
#pragma unroll
    for (int o = 16; o > 0; o >>= 1) {
        s  += __shfl_xor_sync(0xffffffffu, s, o);
        sq += __shfl_xor_sync(0xffffffffu, sq, o);
    }
    __shared__ float ss[8], ssq[8];
    int w = threadIdx.x >> 5, lane = threadIdx.x & 31;
    if (lane == 0) { ss[w] = s; ssq[w] = sq; }
    __syncthreads();
    if (w == 0) {
        s  = (lane < 8) ? ss[lane]  : 0.f;
        sq = (lane < 8) ? ssq[lane] : 0.f;
#pragma unroll
        for (int o = 4; o > 0; o >>= 1) {
            s  += __shfl_xor_sync(0xffffffffu, s, o);
            sq += __shfl_xor_sync(0xffffffffu, sq, o);
        }
        if (lane == 0) { ss[0] = s; ssq[0] = sq; }
    }
    __syncthreads();
    float mu  = ss[0] * (1.f / D_SZ);
    float var = ssq[0] * (1.f / D_SZ) - mu * mu;
    float rs  = rsqrtf(var + 1e-6f);
#pragma unroll
    for (int i = 0; i < 3; i++) {
        int c = threadIdx.x + i * 256;
        g_xn[(size_t)row * D_SZ + c] = (v[i] - mu) * rs * gam[c] + bet[c];
    }
}

// ---------------------------------------------------------------------------
// bf16-split NT GEMM: inline f32->bf16 hi/lo split at STS, ldmatrix mainloop.
// Tile 128x128x32, 512 threads (16 warps 4x4), warp tile 32x32.  (R7 version)
// ---------------------------------------------------------------------------
#define RSB    80                 // smem bytes per row (64 data + 16 pad)
#define TILEB  (128 * RSB)        // 10240
#define STAGEB (4 * TILEB)        // 40960: Ahi, Alo, Bhi, Blo
#define GSMEM  (2 * STAGEB)       // 81920

template <int EPI>
__global__ __launch_bounds__(512)
void mgemm(const float* __restrict__ A, int lda,
           const float* __restrict__ Bm, int ldb,
           float* __restrict__ C, int M, int N, int K,
           const float* __restrict__ bias,
           const float* __restrict__ resid, size_t zC)
{
    extern __shared__ __align__(16) char smraw[];
    uint32_t smbase = s2u(smraw);

    A += (size_t)blockIdx.z * K;
    C += (size_t)blockIdx.z * zC;

    int tid = threadIdx.x;
    int wid = tid >> 5, lane = tid & 31;
    int wm = (wid & 3) * 32;
    int wn = (wid >> 2) * 32;
    int grp = lane >> 2, qd = lane & 3;
    int row0 = blockIdx.y * 128, col0 = blockIdx.x * 128;

    float acc[2][4][4];
#pragma unroll
    for (int mi = 0; mi < 2; mi++)
#pragma unroll
        for (int ni = 0; ni < 4; ni++)
#pragma unroll
            for (int e = 0; e < 4; e++) acc[mi][ni][e] = 0.f;

    const int nch = (K + 31) / 32;

    int lrow = tid >> 2;           // 0..127
    int q    = tid & 3;            // float4 slot pair

    float4 pa[2], pb[2];

    auto loadc = [&](int c) {
        int kc = c * 32;
#pragma unroll
        for (int j = 0; j < 2; j++) {
            int col = kc + q * 8 + j * 4;
            bool kok = col < K;
            pa[j] = kok ? *(const float4*)(A + (size_t)(row0 + lrow) * lda + col)
                        : make_float4(0.f, 0.f, 0.f, 0.f);
            int n = col0 + lrow;
            pb[j] = (kok && n < N) ? *(const float4*)(Bm + (size_t)n * ldb + col)
                                   : make_float4(0.f, 0.f, 0.f, 0.f);
        }
    };

    auto storec = [&](int s) {
        uint32_t st = smbase + (uint32_t)s * STAGEB + lrow * RSB;
#pragma unroll
        for (int j = 0; j < 2; j++) {
            uint32_t co = (q * 8 + j * 4) * 2;
            uint2 h, l;
            split4(pa[j], h, l);
            *(uint2*)(smraw + (st - smbase) + co)             = h;
            *(uint2*)(smraw + (st - smbase) + TILEB + co)     = l;
            split4(pb[j], h, l);
            *(uint2*)(smraw + (st - smbase) + 2 * TILEB + co) = h;
            *(uint2*)(smraw + (st - smbase) + 3 * TILEB + co) = l;
        }
    };

    loadc(0);
    storec(0);
    __syncthreads();

    int arow = lane & 15;
    int asel = (lane >> 4) * 16;
    int brow = ((lane >> 4) << 3) + (lane & 7);
    int bsel = ((lane >> 3) & 1) * 16;

    for (int c = 0; c < nch; c++) {
        int s = c & 1;
        if (c + 1 < nch) loadc(c + 1);

        uint32_t stA  = smbase + (uint32_t)s * STAGEB;
        uint32_t stAl = stA + TILEB;
        uint32_t stB  = stA + 2 * TILEB;
        uint32_t stBl = stA + 3 * TILEB;

#pragma unroll
        for (int ks = 0; ks < 2; ks++) {
            int kb = ks * 32;   // byte offset of k-half
            uint32_t ahi[2][4], alo[2][4], bhi[4][2], blo[4][2];
#pragma unroll
            for (int mi = 0; mi < 2; mi++) {
                uint32_t ad = stA + (wm + mi * 16 + arow) * RSB + kb + asel;
                ldsm4(ahi[mi][0], ahi[mi][1], ahi[mi][2], ahi[mi][3], ad);
            }
#pragma unroll
            for (int nb = 0; nb < 2; nb++) {
                uint32_t bd = stB + (wn + nb * 16 + brow) * RSB + kb + bsel;
                ldsm4(bhi[2 * nb][0], bhi[2 * nb][1],
                      bhi[2 * nb + 1][0], bhi[2 * nb + 1][1], bd);
            }
            // pass 1: hi*hi
#pragma unroll
            for (int mi = 0; mi < 2; mi++)
#pragma unroll
                for (int ni = 0; ni < 4; ni++)
                    mma16(acc[mi][ni], ahi[mi], bhi[ni]);
            // pass 2: lo*hi
#pragma unroll
            for (int mi = 0; mi < 2; mi++) {
                uint32_t ad = stAl + (wm + mi * 16 + arow) * RSB + kb + asel;
                ldsm4(alo[mi][0], alo[mi][1], alo[mi][2], alo[mi][3], ad);
            }
#pragma unroll
            for (int mi = 0; mi < 2; mi++)
#pragma unroll
                for (int ni = 0; ni < 4; ni++)
                    mma16(acc[mi][ni], alo[mi], bhi[ni]);
            // pass 3: hi*lo
#pragma unroll
            for (int nb = 0; nb < 2; nb++) {
                uint32_t bd = stBl + (wn + nb * 16 + brow) * RSB + kb + bsel;
                ldsm4(blo[2 * nb][0], blo[2 * nb][1],
                      blo[2 * nb + 1][0], blo[2 * nb + 1][1], bd);
            }
#pragma unroll
            for (int mi = 0; mi < 2; mi++)
#pragma unroll
                for (int ni = 0; ni < 4; ni++)
                    mma16(acc[mi][ni], ahi[mi], blo[ni]);
        }

        if (c + 1 < nch) storec((c + 1) & 1);
        __syncthreads();
    }

    // epilogue: registers -> gmem
#pragma unroll
    for (int mi = 0; mi < 2; mi++) {
#pragma unroll
        for (int ni = 0; ni < 4; ni++) {
            int r  = row0 + wm + mi * 16 + grp;
            int cc = col0 + wn + ni * 8 + qd * 2;
            if (cc < N) {
#pragma unroll
                for (int h = 0; h < 2; h++) {
                    int rr = r + h * 8;
                    float v0 = acc[mi][ni][h * 2 + 0];
                    float v1 = acc[mi][ni][h * 2 + 1];
                    if (EPI == 1) {
                        v0 += bias[cc];
                        v1 += bias[cc + 1];
                        v0 = (v0 > 20.f) ? v0 : log1pf(__expf(v0));
                        v1 = (v1 > 20.f) ? v1 : log1pf(__expf(v1));
                    } else if (EPI == 2) {
                        v0 = fmaxf(v0, 0.f) + resid[(size_t)rr * N + cc];
                        v1 = fmaxf(v1, 0.f) + resid[(size_t)rr * N + cc + 1];
                    }
                    float2 o; o.x = v0; o.y = v1;
                    *(float2*)(C + (size_t)rr * N + cc) = o;
                }
            }
        }
    }
}

// ---------------------------------------------------------------------------
// Reduce split-K partials for x_dbl
// ---------------------------------------------------------------------------
__global__ void xdbl_reduce_kernel()
{
    int i = blockIdx.x * 256 + threadIdx.x;
    if (i < XPART) {
        float s = g_xpart[i] + g_xpart[i + XPART]
                + g_xpart[i + 2 * XPART] + g_xpart[i + 3 * XPART];
        g_xdbl[i] = s;
    }
}

// ---------------------------------------------------------------------------
// Causal depthwise conv (width 4) + bias + SiLU; 4 outputs per thread.
// ---------------------------------------------------------------------------
__global__ void conv_silu_kernel(const float* __restrict__ Wc,
                                 const float* __restrict__ bc)
{
    int gid = blockIdx.x * blockDim.x + threadIdx.x;
    if (gid >= (M_ROWS / 4) * DI_SZ) return;
    int d   = gid % DI_SZ;
    int blk = gid / DI_SZ;
    int b   = blk / (L_SZ / 4);
    int l0  = (blk % (L_SZ / 4)) * 4;
    int bl0 = b * L_SZ + l0;

    float w0 = Wc[d * 4 + 0], w1 = Wc[d * 4 + 1];
    float w2 = Wc[d * 4 + 2], w3 = Wc[d * 4 + 3];
    float bb = bc[d];

    float x[7];
#pragma unroll
    for (int k = 0; k < 7; k++) {
        int l = l0 - 3 + k;
        x[k] = (l >= 0) ? g_xz[(size_t)(bl0 - 3 + k) * DI2_SZ + d] : 0.f;
    }
#pragma unroll
    for (int i = 0; i < 4; i++) {
        float acc = bb;
        acc = fmaf(w0, x[i],     acc);
        acc = fmaf(w1, x[i + 1], acc);
        acc = fmaf(w2, x[i + 2], acc);
        acc = fmaf(w3, x[i + 3], acc);
        g_xc[(size_t)(bl0 + i) * DI_SZ + d] = acc / (1.f + __expf(-acc));
    }
}

// ---------------------------------------------------------------------------
// Selective scan + skip + gate, 4-step batched:
//  - operands for the next 4 steps prefetched as one 20-load block (MLP)
//  - 4 independent shfl reduction trees interleaved (hides shfl latency)
// 16 lanes per (b,d) chain, 2 chains per warp.
// ---------------------------------------------------------------------------
__global__ __launch_bounds__(256)
void scan_kernel(const float* __restrict__ A_log,
                 const float* __restrict__ Dpar)
{
    int gtid  = blockIdx.x * 256 + threadIdx.x;
    int chain = gtid >> 4;          // 0..6143
    int n     = gtid & 15;
    int b     = chain / DI_SZ;
    int d     = chain % DI_SZ;

    float a  = -__expf(A_log[d * N_ST + n]);
    float dp = Dpar[d];
    float h  = 0.f;
    int base = b * L_SZ;

    const float* pd = g_delta + (size_t)base * DI_SZ + d;
    const float* pu = g_xc    + (size_t)base * DI_SZ + d;
    const float* px = g_xdbl  + (size_t)base * XDBL_W + DTR_SZ + n;
    const float* pz = g_xz    + (size_t)base * DI2_SZ + DI_SZ + d;
    float*       py = g_y     + (size_t)base * DI_SZ + d;

    float dl[4], u[4], Bv[4], Cv[4], z[4];
#pragma unroll
    for (int i = 0; i < 4; i++) {
        dl[i] = pd[i * DI_SZ];
        u[i]  = pu[i * DI_SZ];
        Bv[i] = px[i * XDBL_W];
        Cv[i] = px[i * XDBL_W + N_ST];
        z[i]  = pz[i * DI2_SZ];
    }
    pd += 4 * DI_SZ; pu += 4 * DI_SZ; px += 4 * XDBL_W; pz += 4 * DI2_SZ;

    for (int blk = 0; blk < L_SZ / 4; blk++) {
        float dl2[4], u2[4], Bv2[4], Cv2[4], z2[4];
        if (blk + 1 < L_SZ / 4) {
#pragma unroll
            for (int i = 0; i < 4; i++) {
                dl2[i] = pd[i * DI_SZ];
                u2[i]  = pu[i * DI_SZ];
                Bv2[i] = px[i * XDBL_W];
                Cv2[i] = px[i * XDBL_W + N_ST];
                z2[i]  = pz[i * DI2_SZ];
            }
            pd += 4 * DI_SZ; pu += 4 * DI_SZ; px += 4 * XDBL_W; pz += 4 * DI2_SZ;
        }

        // sequential h updates (cheap chain), collect 4 partial sums
        float s0, s1, s2, s3;
        {
            float dA;
            dA = __expf(dl[0] * a); h = fmaf(dA, h, dl[0] * Bv[0] * u[0]); s0 = h * Cv[0];
            dA = __expf(dl[1] * a); h = fmaf(dA, h, dl[1] * Bv[1] * u[1]); s1 = h * Cv[1];
            dA = __expf(dl[2] * a); h = fmaf(dA, h, dl[2] * Bv[2] * u[2]); s2 = h * Cv[2];
            dA = __expf(dl[3] * a); h = fmaf(dA, h, dl[3] * Bv[3] * u[3]); s3 = h * Cv[3];
        }

        // 4 independent reduction trees, interleaved
#pragma unroll
        for (int o = 8; o > 0; o >>= 1) {
            s0 += __shfl_xor_sync(0xffffffffu, s0, o);
            s1 += __shfl_xor_sync(0xffffffffu, s1, o);
            s2 += __shfl_xor_sync(0xffffffffu, s2, o);
            s3 += __shfl_xor_sync(0xffffffffu, s3, o);
        }

        if (n == 0) {
            float sv[4] = {s0, s1, s2, s3};
#pragma unroll
            for (int i = 0; i < 4; i++) {
                float sil = z[i] / (1.f + __expf(-z[i]));
                py[i * DI_SZ] = (sv[i] + u[i] * dp) * sil;
            }
        }
        py += 4 * DI_SZ;

#pragma unroll
        for (int i = 0; i < 4; i++) {
            dl[i] = dl2[i]; u[i] = u2[i]; Bv[i] = Bv2[i]; Cv[i] = Cv2[i]; z[i] = z2[i];
        }
    }
}

// ---------------------------------------------------------------------------
extern "C" void kernel_launch(void* const* d_in, const int* in_sizes, int n_in,
                              void* d_out, int out_size)
{
    const float* input   = (const float*)d_in[0];
    const float* ln_g    = (const float*)d_in[1];
    const float* ln_b    = (const float*)d_in[2];
    const float* W_in    = (const float*)d_in[3];
    const float* W_conv  = (const float*)d_in[4];
    const float* b_conv  = (const float*)d_in[5];
    const float* W_x     = (const float*)d_in[6];
    const float* W_dt    = (const float*)d_in[7];
    const float* b_dt    = (const float*)d_in[8];
    const float* A_log   = (const float*)d_in[9];
    const float* D_param = (const float*)d_in[10];
    const float* W_out   = (const float*)d_in[11];
    float* out = (float*)d_out;

    float *xn, *xz, *xc, *xpart, *xdbl, *delta, *y;
    cudaGetSymbolAddress((void**)&xn,    g_xn);
    cudaGetSymbolAddress((void**)&xz,    g_xz);
    cudaGetSymbolAddress((void**)&xc,    g_xc);
    cudaGetSymbolAddress((void**)&xpart, g_xpart);
    cudaGetSymbolAddress((void**)&xdbl,  g_xdbl);
    cudaGetSymbolAddress((void**)&delta, g_delta);
    cudaGetSymbolAddress((void**)&y,     g_y);

    cudaFuncSetAttribute(mgemm<0>, cudaFuncAttributeMaxDynamicSharedMemorySize, GSMEM);
    cudaFuncSetAttribute(mgemm<1>, cudaFuncAttributeMaxDynamicSharedMemorySize, GSMEM);
    cudaFuncSetAttribute(mgemm<2>, cudaFuncAttributeMaxDynamicSharedMemorySize, GSMEM);

    // 1. LayerNorm
    ln_kernel<<<M_ROWS, 256>>>(input, ln_g, ln_b);

    // 2. in-proj: xz = xn @ W_in^T   (4096 x 3072 x 768)
    {
        dim3 g(DI2_SZ / 128, M_ROWS / 128, 1);
        mgemm<0><<<g, 512, GSMEM>>>(xn, D_SZ, W_in, D_SZ, xz,
                                    M_ROWS, DI2_SZ, D_SZ, nullptr, nullptr, 0);
    }

    // 3. causal depthwise conv + SiLU -> xc
    {
        int total = (M_ROWS / 4) * DI_SZ;
        conv_silu_kernel<<<(total + 255) / 256, 256>>>(W_conv, b_conv);
    }

    // 4. x_dbl = xc @ W_x^T   (4096 x 80 x 1536) — split-K x4
    {
        dim3 g(1, M_ROWS / 128, KSPLIT);
        mgemm<0><<<g, 512, GSMEM>>>(xc, DI_SZ, W_x, DI_SZ, xpart,
                                    M_ROWS, XDBL_W, DI_SZ / KSPLIT,
                                    nullptr, nullptr, (size_t)XPART);
        xdbl_reduce_kernel<<<(XPART + 255) / 256, 256>>>();
    }

    // 5. delta = softplus(dt @ W_dt^T + b_dt)   (4096 x 1536 x 48)
    {
        dim3 g(DI_SZ / 128, M_ROWS / 128, 1);
        mgemm<1><<<g, 512, GSMEM>>>(xdbl, XDBL_W, W_dt, DTR_SZ, delta,
                                    M_ROWS, DI_SZ, DTR_SZ, b_dt, nullptr, 0);
    }

    // 6. selective scan + skip + gating -> y
    {
        int threads = B_SZ * DI_SZ * N_ST;   // 98304
        scan_kernel<<<threads / 256, 256>>>(A_log, D_param);
    }

    // 7. out = relu(y @ W_out^T) + input   (4096 x 768 x 1536)
    {
        dim3 g(D_SZ / 128, M_ROWS / 128, 1);
        mgemm<2><<<g, 512, GSMEM>>>(y, DI_SZ, W_out, DI_SZ, out,
                                    M_ROWS, D_SZ, DI_SZ, nullptr, input, 0);
    }
}

// round 10
// speedup vs baseline: 1.6209x; 1.1422x over previous
#include <cuda_runtime.h>
#include <cuda_bf16.h>
#include <math.h>
#include <stdint.h>

// Problem constants
#define B_SZ   4
#define L_SZ   1024
#define D_SZ   768
#define DI_SZ  1536
#define DI2_SZ 3072
#define N_ST   16
#define DTR_SZ 48
#define XDBL_W 80           // DTR + 2*N
#define M_ROWS 4096         // B*L
#define KSPLIT 4
#define XPART  (M_ROWS * XDBL_W)

// Scratch (device globals; no allocation allowed)
__device__ float g_xn  [M_ROWS * D_SZ];
__device__ float g_xz  [M_ROWS * DI2_SZ];
__device__ float g_xc  [M_ROWS * DI_SZ];
__device__ float g_xpart[KSPLIT * XPART];
__device__ float g_xdbl[M_ROWS * XDBL_W];
__device__ float g_delta[M_ROWS * DI_SZ];
__device__ float g_y   [M_ROWS * DI_SZ];

__device__ __forceinline__ void mma16(float* d,
                                      const uint32_t* a, const uint32_t* b) {
    asm volatile(
        "mma.sync.aligned.m16n8k16.row.col.f32.bf16.bf16.f32 "
        "{%0,%1,%2,%3}, {%4,%5,%6,%7}, {%8,%9}, {%0,%1,%2,%3};"
        : "+f"(d[0]), "+f"(d[1]), "+f"(d[2]), "+f"(d[3])
        : "r"(a[0]), "r"(a[1]), "r"(a[2]), "r"(a[3]), "r"(b[0]), "r"(b[1]));
}

__device__ __forceinline__ void ldsm4(uint32_t& r0, uint32_t& r1,
                                      uint32_t& r2, uint32_t& r3, uint32_t a) {
    asm volatile("ldmatrix.sync.aligned.m8n8.x4.shared.b16 {%0,%1,%2,%3}, [%4];"
                 : "=r"(r0), "=r"(r1), "=r"(r2), "=r"(r3) : "r"(a));
}

__device__ __forceinline__ uint32_t s2u(const void* p) {
    uint32_t a;
    asm("{ .reg .u64 t; cvta.to.shared.u64 t, %1; cvt.u32.u64 %0, t; }"
        : "=r"(a) : "l"(p));
    return a;
}

// split float4 into 4x bf16 hi (8B) and 4x bf16 lo (8B)
__device__ __forceinline__ void split4(float4 v, uint2& h, uint2& l) {
    __nv_bfloat16 hx = __float2bfloat16_rn(v.x);
    __nv_bfloat16 hy = __float2bfloat16_rn(v.y);
    __nv_bfloat16 hz = __float2bfloat16_rn(v.z);
    __nv_bfloat16 hw = __float2bfloat16_rn(v.w);
    __nv_bfloat162 h0 = __halves2bfloat162(hx, hy);
    __nv_bfloat162 h1 = __halves2bfloat162(hz, hw);
    __nv_bfloat162 l0 = __halves2bfloat162(
        __float2bfloat16_rn(v.x - __bfloat162float(hx)),
        __float2bfloat16_rn(v.y - __bfloat162float(hy)));
    __nv_bfloat162 l1 = __halves2bfloat162(
        __float2bfloat16_rn(v.z - __bfloat162float(hz)),
        __float2bfloat16_rn(v.w - __bfloat162float(hw)));
    h.x = *(uint32_t*)&h0; h.y = *(uint32_t*)&h1;
    l.x = *(uint32_t*)&l0; l.y = *(uint32_t*)&l1;
}

// hi-only pack: float4 -> 4x bf16 (8B)
__device__ __forceinline__ uint2 hi4(float4 v) {
    __nv_bfloat162 h0 = __floats2bfloat162_rn(v.x, v.y);
    __nv_bfloat162 h1 = __floats2bfloat162_rn(v.z, v.w);
    uint2 r;
    r.x = *(uint32_t*)&h0; r.y = *(uint32_t*)&h1;
    return r;
}

// ---------------------------------------------------------------------------
// LayerNorm: one block (256 thr) per row of 768
// ---------------------------------------------------------------------------
__global__ void ln_kernel(const float* __restrict__ x,
                          const float* __restrict__ gam,
                          const float* __restrict__ bet)
{
    int row = blockIdx.x;
    const float* xr = x + (size_t)row * D_SZ;
    float v[3];
    float s = 0.f, sq = 0.f;
#pragma unroll
    for (int i = 0; i < 3; i++) {
        v[i] = xr[threadIdx.x + i * 256];
        s += v[i];
        sq += v[i] * v[i];
    }
#pragma unroll
    for (int o = 16; o > 0; o >>= 1) {
        s  += __shfl_xor_sync(0xffffffffu, s, o);
        sq += __shfl_xor_sync(0xffffffffu, sq, o);
    }
    __shared__ float ss[8], ssq[8];
    int w = threadIdx.x >> 5, lane = threadIdx.x & 31;
    if (lane == 0) { ss[w] = s; ssq[w] = sq; }
    __syncthreads();
    if (w == 0) {
        s  = (lane < 8) ? ss[lane]  : 0.f;
        sq = (lane < 8) ? ssq[lane] : 0.f;
#pragma unroll
        for (int o = 4; o > 0; o >>= 1) {
            s  += __shfl_xor_sync(0xffffffffu, s, o);
            sq += __shfl_xor_sync(0xffffffffu, sq, o);
        }
        if (lane == 0) { ss[0] = s; ssq[0] = sq; }
    }
    __syncthreads();
    float mu  = ss[0] * (1.f / D_SZ);
    float var = ssq[0] * (1.f / D_SZ) - mu * mu;
    float rs  = rsqrtf(var + 1e-6f);
#pragma unroll
    for (int i = 0; i < 3; i++) {
        int c = threadIdx.x + i * 256;
        g_xn[(size_t)row * D_SZ + c] = (v[i] - mu) * rs * gam[c] + bet[c];
    }
}

// ---------------------------------------------------------------------------
// bf16-split NT GEMM: inline f32->bf16 hi/lo split at STS, ldmatrix mainloop.
// Tile 128x128x32, 512 threads (16 warps 4x4), warp tile 32x32.
// NPASS=3: hi*hi + lo*hi + hi*lo (err ~5e-7); NPASS=2: hi*hi + lo*hi (~2e-4)
// EPI 0: plain   EPI 1: softplus(acc + bias[n])   EPI 2: relu(acc)+resid
// ---------------------------------------------------------------------------
#define RSB    80                 // smem bytes per row (64 data + 16 pad)
#define TILEB  (128 * RSB)        // 10240
#define STAGEB (4 * TILEB)        // 40960: Ahi, Alo, Bhi, Blo
#define GSMEM  (2 * STAGEB)       // 81920

template <int EPI, int NPASS>
__global__ __launch_bounds__(512)
void mgemm(const float* __restrict__ A, int lda,
           const float* __restrict__ Bm, int ldb,
           float* __restrict__ C, int M, int N, int K,
           const float* __restrict__ bias,
           const float* __restrict__ resid, size_t zC)
{
    extern __shared__ __align__(16) char smraw[];
    uint32_t smbase = s2u(smraw);

    A += (size_t)blockIdx.z * K;
    C += (size_t)blockIdx.z * zC;

    int tid = threadIdx.x;
    int wid = tid >> 5, lane = tid & 31;
    int wm = (wid & 3) * 32;
    int wn = (wid >> 2) * 32;
    int grp = lane >> 2, qd = lane & 3;
    int row0 = blockIdx.y * 128, col0 = blockIdx.x * 128;

    float acc[2][4][4];
#pragma unroll
    for (int mi = 0; mi < 2; mi++)
#pragma unroll
        for (int ni = 0; ni < 4; ni++)
#pragma unroll
            for (int e = 0; e < 4; e++) acc[mi][ni][e] = 0.f;

    const int nch = (K + 31) / 32;

    int lrow = tid >> 2;           // 0..127
    int q    = tid & 3;            // float4 slot pair

    float4 pa[2], pb[2];

    auto loadc = [&](int c) {
        int kc = c * 32;
#pragma unroll
        for (int j = 0; j < 2; j++) {
            int col = kc + q * 8 + j * 4;
            bool kok = col < K;
            pa[j] = kok ? *(const float4*)(A + (size_t)(row0 + lrow) * lda + col)
                        : make_float4(0.f, 0.f, 0.f, 0.f);
            int n = col0 + lrow;
            pb[j] = (kok && n < N) ? *(const float4*)(Bm + (size_t)n * ldb + col)
                                   : make_float4(0.f, 0.f, 0.f, 0.f);
        }
    };

    auto storec = [&](int s) {
        uint32_t st = smbase + (uint32_t)s * STAGEB + lrow * RSB;
#pragma unroll
        for (int j = 0; j < 2; j++) {
            uint32_t co = (q * 8 + j * 4) * 2;
            uint2 h, l;
            split4(pa[j], h, l);         // A always hi+lo
            *(uint2*)(smraw + (st - smbase) + co)             = h;
            *(uint2*)(smraw + (st - smbase) + TILEB + co)     = l;
            if (NPASS == 3) {
                split4(pb[j], h, l);
                *(uint2*)(smraw + (st - smbase) + 2 * TILEB + co) = h;
                *(uint2*)(smraw + (st - smbase) + 3 * TILEB + co) = l;
            } else {
                *(uint2*)(smraw + (st - smbase) + 2 * TILEB + co) = hi4(pb[j]);
            }
        }
    };

    loadc(0);
    storec(0);
    __syncthreads();

    int arow = lane & 15;
    int asel = (lane >> 4) * 16;
    int brow = ((lane >> 4) << 3) + (lane & 7);
    int bsel = ((lane >> 3) & 1) * 16;

    for (int c = 0; c < nch; c++) {
        int s = c & 1;
        if (c + 1 < nch) loadc(c + 1);

        uint32_t stA  = smbase + (uint32_t)s * STAGEB;
        uint32_t stAl = stA + TILEB;
        uint32_t stB  = stA + 2 * TILEB;
        uint32_t stBl = stA + 3 * TILEB;

#pragma unroll
        for (int ks = 0; ks < 2; ks++) {
            int kb = ks * 32;   // byte offset of k-half
            uint32_t ahi[2][4], alo[2][4], bhi[4][2], blo[4][2];
#pragma unroll
            for (int mi = 0; mi < 2; mi++) {
                uint32_t ad = stA + (wm + mi * 16 + arow) * RSB + kb + asel;
                ldsm4(ahi[mi][0], ahi[mi][1], ahi[mi][2], ahi[mi][3], ad);
            }
#pragma unroll
            for (int nb = 0; nb < 2; nb++) {
                uint32_t bd = stB + (wn + nb * 16 + brow) * RSB + kb + bsel;
                ldsm4(bhi[2 * nb][0], bhi[2 * nb][1],
                      bhi[2 * nb + 1][0], bhi[2 * nb + 1][1], bd);
            }
            // pass 1: hi*hi
#pragma unroll
            for (int mi = 0; mi < 2; mi++)
#pragma unroll
                for (int ni = 0; ni < 4; ni++)
                    mma16(acc[mi][ni], ahi[mi], bhi[ni]);
            // pass 2: lo*hi
#pragma unroll
            for (int mi = 0; mi < 2; mi++) {
                uint32_t ad = stAl + (wm + mi * 16 + arow) * RSB + kb + asel;
                ldsm4(alo[mi][0], alo[mi][1], alo[mi][2], alo[mi][3], ad);
            }
#pragma unroll
            for (int mi = 0; mi < 2; mi++)
#pragma unroll
                for (int ni = 0; ni < 4; ni++)
                    mma16(acc[mi][ni], alo[mi], bhi[ni]);
            // pass 3: hi*lo (full precision only)
            if (NPASS == 3) {
#pragma unroll
                for (int nb = 0; nb < 2; nb++) {
                    uint32_t bd = stBl + (wn + nb * 16 + brow) * RSB + kb + bsel;
                    ldsm4(blo[2 * nb][0], blo[2 * nb][1],
                          blo[2 * nb + 1][0], blo[2 * nb + 1][1], bd);
                }
#pragma unroll
                for (int mi = 0; mi < 2; mi++)
#pragma unroll
                    for (int ni = 0; ni < 4; ni++)
                        mma16(acc[mi][ni], ahi[mi], blo[ni]);
            }
        }

        if (c + 1 < nch) storec((c + 1) & 1);
        __syncthreads();
    }

    // epilogue: registers -> gmem
#pragma unroll
    for (int mi = 0; mi < 2; mi++) {
#pragma unroll
        for (int ni = 0; ni < 4; ni++) {
            int r  = row0 + wm + mi * 16 + grp;
            int cc = col0 + wn + ni * 8 + qd * 2;
            if (cc < N) {
#pragma unroll
                for (int h = 0; h < 2; h++) {
                    int rr = r + h * 8;
                    float v0 = acc[mi][ni][h * 2 + 0];
                    float v1 = acc[mi][ni][h * 2 + 1];
                    if (EPI == 1) {
                        v0 += bias[cc];
                        v1 += bias[cc + 1];
                        v0 = (v0 > 20.f) ? v0 : log1pf(__expf(v0));
                        v1 = (v1 > 20.f) ? v1 : log1pf(__expf(v1));
                    } else if (EPI == 2) {
                        v0 = fmaxf(v0, 0.f) + resid[(size_t)rr * N + cc];
                        v1 = fmaxf(v1, 0.f) + resid[(size_t)rr * N + cc + 1];
                    }
                    float2 o; o.x = v0; o.y = v1;
                    *(float2*)(C + (size_t)rr * N + cc) = o;
                }
            }
        }
    }
}

// ---------------------------------------------------------------------------
// Reduce split-K partials for x_dbl
// ---------------------------------------------------------------------------
__global__ void xdbl_reduce_kernel()
{
    int i = blockIdx.x * 256 + threadIdx.x;
    if (i < XPART) {
        float s = g_xpart[i] + g_xpart[i + XPART]
                + g_xpart[i + 2 * XPART] + g_xpart[i + 3 * XPART];
        g_xdbl[i] = s;
    }
}

// ---------------------------------------------------------------------------
// Causal depthwise conv (width 4) + bias + SiLU; 4 outputs per thread.
// ---------------------------------------------------------------------------
__global__ void conv_silu_kernel(const float* __restrict__ Wc,
                                 const float* __restrict__ bc)
{
    int gid = blockIdx.x * blockDim.x + threadIdx.x;
    if (gid >= (M_ROWS / 4) * DI_SZ) return;
    int d   = gid % DI_SZ;
    int blk = gid / DI_SZ;
    int b   = blk / (L_SZ / 4);
    int l0  = (blk % (L_SZ / 4)) * 4;
    int bl0 = b * L_SZ + l0;

    float w0 = Wc[d * 4 + 0], w1 = Wc[d * 4 + 1];
    float w2 = Wc[d * 4 + 2], w3 = Wc[d * 4 + 3];
    float bb = bc[d];

    float x[7];
#pragma unroll
    for (int k = 0; k < 7; k++) {
        int l = l0 - 3 + k;
        x[k] = (l >= 0) ? g_xz[(size_t)(bl0 - 3 + k) * DI2_SZ + d] : 0.f;
    }
#pragma unroll
    for (int i = 0; i < 4; i++) {
        float acc = bb;
        acc = fmaf(w0, x[i],     acc);
        acc = fmaf(w1, x[i + 1], acc);
        acc = fmaf(w2, x[i + 2], acc);
        acc = fmaf(w3, x[i + 3], acc);
        g_xc[(size_t)(bl0 + i) * DI_SZ + d] = acc / (1.f + __expf(-acc));
    }
}

// ---------------------------------------------------------------------------
// Selective scan + skip + gate, 4-step batched (R9 version).
// ---------------------------------------------------------------------------
__global__ __launch_bounds__(256)
void scan_kernel(const float* __restrict__ A_log,
                 const float* __restrict__ Dpar)
{
    int gtid  = blockIdx.x * 256 + threadIdx.x;
    int chain = gtid >> 4;          // 0..6143
    int n     = gtid & 15;
    int b     = chain / DI_SZ;
    int d     = chain % DI_SZ;

    float a  = -__expf(A_log[d * N_ST + n]);
    float dp = Dpar[d];
    float h  = 0.f;
    int base = b * L_SZ;

    const float* pd = g_delta + (size_t)base * DI_SZ + d;
    const float* pu = g_xc    + (size_t)base * DI_SZ + d;
    const float* px = g_xdbl  + (size_t)base * XDBL_W + DTR_SZ + n;
    const float* pz = g_xz    + (size_t)base * DI2_SZ + DI_SZ + d;
    float*       py = g_y     + (size_t)base * DI_SZ + d;

    float dl[4], u[4], Bv[4], Cv[4], z[4];
#pragma unroll
    for (int i = 0; i < 4; i++) {
        dl[i] = pd[i * DI_SZ];
        u[i]  = pu[i * DI_SZ];
        Bv[i] = px[i * XDBL_W];
        Cv[i] = px[i * XDBL_W + N_ST];
        z[i]  = pz[i * DI2_SZ];
    }
    pd += 4 * DI_SZ; pu += 4 * DI_SZ; px += 4 * XDBL_W; pz += 4 * DI2_SZ;

    for (int blk = 0; blk < L_SZ / 4; blk++) {
        float dl2[4], u2[4], Bv2[4], Cv2[4], z2[4];
        if (blk + 1 < L_SZ / 4) {
#pragma unroll
            for (int i = 0; i < 4; i++) {
                dl2[i] = pd[i * DI_SZ];
                u2[i]  = pu[i * DI_SZ];
                Bv2[i] = px[i * XDBL_W];
                Cv2[i] = px[i * XDBL_W + N_ST];
                z2[i]  = pz[i * DI2_SZ];
            }
            pd += 4 * DI_SZ; pu += 4 * DI_SZ; px += 4 * XDBL_W; pz += 4 * DI2_SZ;
        }

        float s0, s1, s2, s3;
        {
            float dA;
            dA = __expf(dl[0] * a); h = fmaf(dA, h, dl[0] * Bv[0] * u[0]); s0 = h * Cv[0];
            dA = __expf(dl[1] * a); h = fmaf(dA, h, dl[1] * Bv[1] * u[1]); s1 = h * Cv[1];
            dA = __expf(dl[2] * a); h = fmaf(dA, h, dl[2] * Bv[2] * u[2]); s2 = h * Cv[2];
            dA = __expf(dl[3] * a); h = fmaf(dA, h, dl[3] * Bv[3] * u[3]); s3 = h * Cv[3];
        }

#pragma unroll
        for (int o = 8; o > 0; o >>= 1) {
            s0 += __shfl_xor_sync(0xffffffffu, s0, o);
            s1 += __shfl_xor_sync(0xffffffffu, s1, o);
            s2 += __shfl_xor_sync(0xffffffffu, s2, o);
            s3 += __shfl_xor_sync(0xffffffffu, s3, o);
        }

        if (n == 0) {
            float sv[4] = {s0, s1, s2, s3};
#pragma unroll
            for (int i = 0; i < 4; i++) {
                float sil = z[i] / (1.f + __expf(-z[i]));
                py[i * DI_SZ] = (sv[i] + u[i] * dp) * sil;
            }
        }
        py += 4 * DI_SZ;

#pragma unroll
        for (int i = 0; i < 4; i++) {
            dl[i] = dl2[i]; u[i] = u2[i]; Bv[i] = Bv2[i]; Cv[i] = Cv2[i]; z[i] = z2[i];
        }
    }
}

// ---------------------------------------------------------------------------
extern "C" void kernel_launch(void* const* d_in, const int* in_sizes, int n_in,
                              void* d_out, int out_size)
{
    const float* input   = (const float*)d_in[0];
    const float* ln_g    = (const float*)d_in[1];
    const float* ln_b    = (const float*)d_in[2];
    const float* W_in    = (const float*)d_in[3];
    const float* W_conv  = (const float*)d_in[4];
    const float* b_conv  = (const float*)d_in[5];
    const float* W_x     = (const float*)d_in[6];
    const float* W_dt    = (const float*)d_in[7];
    const float* b_dt    = (const float*)d_in[8];
    const float* A_log   = (const float*)d_in[9];
    const float* D_param = (const float*)d_in[10];
    const float* W_out   = (const float*)d_in[11];
    float* out = (float*)d_out;

    float *xn, *xz, *xc, *xpart, *xdbl, *delta, *y;
    cudaGetSymbolAddress((void**)&xn,    g_xn);
    cudaGetSymbolAddress((void**)&xz,    g_xz);
    cudaGetSymbolAddress((void**)&xc,    g_xc);
    cudaGetSymbolAddress((void**)&xpart, g_xpart);
    cudaGetSymbolAddress((void**)&xdbl,  g_xdbl);
    cudaGetSymbolAddress((void**)&delta, g_delta);
    cudaGetSymbolAddress((void**)&y,     g_y);

    cudaFuncSetAttribute(mgemm<0,2>, cudaFuncAttributeMaxDynamicSharedMemorySize, GSMEM);
    cudaFuncSetAttribute(mgemm<0,3>, cudaFuncAttributeMaxDynamicSharedMemorySize, GSMEM);
    cudaFuncSetAttribute(mgemm<1,3>, cudaFuncAttributeMaxDynamicSharedMemorySize, GSMEM);
    cudaFuncSetAttribute(mgemm<2,2>, cudaFuncAttributeMaxDynamicSharedMemorySize, GSMEM);

    // 1. LayerNorm
    ln_kernel<<<M_ROWS, 256>>>(input, ln_g, ln_b);

    // 2. in-proj: xz = xn @ W_in^T   (4096 x 3072 x 768) — 2-pass
    {
        dim3 g(DI2_SZ / 128, M_ROWS / 128, 1);
        mgemm<0,2><<<g, 512, GSMEM>>>(xn, D_SZ, W_in, D_SZ, xz,
                                      M_ROWS, DI2_SZ, D_SZ, nullptr, nullptr, 0);
    }

    // 3. causal depthwise conv + SiLU -> xc
    {
        int total = (M_ROWS / 4) * DI_SZ;
        conv_silu_kernel<<<(total + 255) / 256, 256>>>(W_conv, b_conv);
    }

    // 4. x_dbl = xc @ W_x^T   (4096 x 80 x 1536) — split-K x4, 3-pass
    {
        dim3 g(1, M_ROWS / 128, KSPLIT);
        mgemm<0,3><<<g, 512, GSMEM>>>(xc, DI_SZ, W_x, DI_SZ, xpart,
                                      M_ROWS, XDBL_W, DI_SZ / KSPLIT,
                                      nullptr, nullptr, (size_t)XPART);
        xdbl_reduce_kernel<<<(XPART + 255) / 256, 256>>>();
    }

    // 5. delta = softplus(dt @ W_dt^T + b_dt)   (4096 x 1536 x 48) — 3-pass
    {
        dim3 g(DI_SZ / 128, M_ROWS / 128, 1);
        mgemm<1,3><<<g, 512, GSMEM>>>(xdbl, XDBL_W, W_dt, DTR_SZ, delta,
                                      M_ROWS, DI_SZ, DTR_SZ, b_dt, nullptr, 0);
    }

    // 6. selective scan + skip + gating -> y
    {
        int threads = B_SZ * DI_SZ * N_ST;   // 98304
        scan_kernel<<<threads / 256, 256>>>(A_log, D_param);
    }

    // 7. out = relu(y @ W_out^T) + input   (4096 x 768 x 1536) — 2-pass
    {
        dim3 g(D_SZ / 128, M_ROWS / 128, 1);
        mgemm<2,2><<<g, 512, GSMEM>>>(y, DI_SZ, W_out, DI_SZ, out,
                                      M_ROWS, D_SZ, DI_SZ, nullptr, input, 0);
    }
}